// round 5
// baseline (speedup 1.0000x reference)
#include <cuda_runtime.h>
#include <cstdint>

// Problem constants
#define BB 32
#define SS 2048
#define HH 1024

// Scratch (no allocations allowed)
__device__ float g_t[BB * HH];       // q_proj + Wa_b + Ua_b, per (b,k)
__device__ float g_scores[BB * SS];  // attention scores

// ---------------------------------------------------------------------------
// helpers
// ---------------------------------------------------------------------------
__device__ __forceinline__ unsigned f2tf(float f) {
    unsigned r;
    asm("cvt.rna.tf32.f32 %0, %1;" : "=r"(r) : "f"(f));
    return r;
}

__device__ __forceinline__ void cp16(float* dst, const float* src) {
    unsigned d = (unsigned)__cvta_generic_to_shared(dst);
    asm volatile("cp.async.cg.shared.global [%0], [%1], 16;" :: "r"(d), "l"(src));
}

__device__ __forceinline__ void mma_tf32(float c[4], const unsigned a[4],
                                         unsigned b0, unsigned b1) {
    asm volatile(
        "mma.sync.aligned.m16n8k8.row.col.f32.tf32.tf32.f32 "
        "{%0,%1,%2,%3},{%4,%5,%6,%7},{%8,%9},{%0,%1,%2,%3};"
        : "+f"(c[0]), "+f"(c[1]), "+f"(c[2]), "+f"(c[3])
        : "r"(a[0]), "r"(a[1]), "r"(a[2]), "r"(a[3]), "r"(b0), "r"(b1));
}

// ---------------------------------------------------------------------------
// Kernel 0: init scores = Va_b, context region of d_out = 0
// ---------------------------------------------------------------------------
__global__ void k_init(const float* __restrict__ Va_b, float* __restrict__ ctx) {
    int i = blockIdx.x * blockDim.x + threadIdx.x;
    if (i < BB * SS) g_scores[i] = Va_b[0];
    if (i < BB * HH) ctx[i] = 0.0f;
}

// ---------------------------------------------------------------------------
// Kernel 1: g_t[b,k] = sum_h query[b,h] * Wa_w[k,h] + Wa_b[k] + Ua_b[k]
// one warp per (b,k)
// ---------------------------------------------------------------------------
__global__ void __launch_bounds__(256) k_qproj(const float* __restrict__ q,
                                               const float* __restrict__ W,
                                               const float* __restrict__ Wb,
                                               const float* __restrict__ Ub) {
    int w = (blockIdx.x * blockDim.x + threadIdx.x) >> 5;
    int lane = threadIdx.x & 31;
    int b = w >> 10;          // / HH (1024)
    int k = w & 1023;
    const float* qr = q + (size_t)b * HH;
    const float* wr = W + (size_t)k * HH;
    float acc = 0.0f;
#pragma unroll 8
    for (int h = lane; h < HH; h += 32) acc += qr[h] * wr[h];
#pragma unroll
    for (int o = 16; o; o >>= 1) acc += __shfl_xor_sync(0xffffffffu, acc, o);
    if (lane == 0) g_t[b * HH + k] = acc + Wb[k] + Ub[k];
}

// ---------------------------------------------------------------------------
// Kernel 2 (main): fused  tanh(keys@Ua^T + t) . Va  ->  atomic scores
// CTA tile: 128 (s) x 128 (k_out), K-chunk 32, tf32 mma.sync, cp.async pipeline
// grid: (S/128=16, H/128=8, B=32), 256 threads (8 warps, 2x4 warp grid)
// ---------------------------------------------------------------------------
#define SROW 36                 // padded smem row stride (floats) -> conflict free
#define TILEF (128 * SROW)      // floats per tile buffer

__global__ void __launch_bounds__(256) k_main(const float* __restrict__ keys,
                                              const float* __restrict__ Ua,
                                              const float* __restrict__ Va) {
    extern __shared__ float sm[];
    float* Abuf[2] = { sm,           sm + 2 * TILEF };
    float* Bbuf[2] = { sm + TILEF,   sm + 3 * TILEF };

    const int b  = blockIdx.z;
    const int s0 = blockIdx.x * 128;
    const int k0 = blockIdx.y * 128;
    const int tid = threadIdx.x;

    const float* Ag = keys + ((size_t)b * SS + s0) * HH;   // + row*HH + h
    const float* Bg = Ua + (size_t)k0 * HH;                // + row*HH + h

    const int lane = tid & 31, warp = tid >> 5;
    const int wm = warp >> 2, wn = warp & 3;               // 2 x 4 warp grid
    const int grp = lane >> 2, tid4 = lane & 3;

    float c[4][4][4];
#pragma unroll
    for (int mi = 0; mi < 4; mi++)
#pragma unroll
        for (int ni = 0; ni < 4; ni++)
#pragma unroll
            for (int r = 0; r < 4; r++) c[mi][ni][r] = 0.0f;

    // loader: 128 rows x 32 floats per tile; 256 threads x 4 float4 each (A and B)
    auto load_stage = [&](int st, int h0) {
#pragma unroll
        for (int p = 0; p < 4; p++) {
            int id  = tid + p * 256;
            int row = id >> 3;
            int c4  = (id & 7) * 4;
            cp16(Abuf[st] + row * SROW + c4, Ag + (size_t)row * HH + h0 + c4);
            cp16(Bbuf[st] + row * SROW + c4, Bg + (size_t)row * HH + h0 + c4);
        }
    };

    int cur = 0;
    load_stage(0, 0);
    asm volatile("cp.async.commit_group;");

#pragma unroll 1
    for (int it = 0; it < HH / 32; ++it) {
        if (it < HH / 32 - 1) {
            load_stage(cur ^ 1, (it + 1) * 32);
            asm volatile("cp.async.commit_group;");
            asm volatile("cp.async.wait_group 1;");
        } else {
            asm volatile("cp.async.wait_group 0;");
        }
        __syncthreads();

        const float* A_ = Abuf[cur];
        const float* B_ = Bbuf[cur];
#pragma unroll
        for (int ks = 0; ks < 4; ++ks) {
            unsigned af[4][4];
#pragma unroll
            for (int mi = 0; mi < 4; mi++) {
                const float* ap = A_ + (wm * 64 + mi * 16 + grp) * SROW + ks * 8 + tid4;
                af[mi][0] = f2tf(ap[0]);
                af[mi][1] = f2tf(ap[8 * SROW]);
                af[mi][2] = f2tf(ap[4]);
                af[mi][3] = f2tf(ap[8 * SROW + 4]);
            }
#pragma unroll
            for (int ni = 0; ni < 4; ni++) {
                const float* bp = B_ + (wn * 32 + ni * 8 + grp) * SROW + ks * 8 + tid4;
                unsigned b0 = f2tf(bp[0]);
                unsigned b1 = f2tf(bp[4]);
#pragma unroll
                for (int mi = 0; mi < 4; mi++) mma_tf32(c[mi][ni], af[mi], b0, b1);
            }
        }
        __syncthreads();
        cur ^= 1;
    }

    // ---- epilogue: tanh(C + t) * Va, reduce over k within tile ----
    float* part = sm;                 // reuse tile smem (safe after trailing sync)
    if (tid < 128) part[tid] = 0.0f;
    __syncthreads();

    float tk[8], vv[8];
#pragma unroll
    for (int ni = 0; ni < 4; ni++) {
        int kc = k0 + wn * 32 + ni * 8 + 2 * tid4;
        tk[ni * 2]     = g_t[b * HH + kc];
        tk[ni * 2 + 1] = g_t[b * HH + kc + 1];
        vv[ni * 2]     = Va[kc];
        vv[ni * 2 + 1] = Va[kc + 1];
    }

    float rs[8];
#pragma unroll
    for (int r = 0; r < 8; r++) rs[r] = 0.0f;
#pragma unroll
    for (int mi = 0; mi < 4; mi++)
#pragma unroll
        for (int ni = 0; ni < 4; ni++) {
            rs[mi * 2]     += tanhf(c[mi][ni][0] + tk[ni * 2])     * vv[ni * 2]
                            + tanhf(c[mi][ni][1] + tk[ni * 2 + 1]) * vv[ni * 2 + 1];
            rs[mi * 2 + 1] += tanhf(c[mi][ni][2] + tk[ni * 2])     * vv[ni * 2]
                            + tanhf(c[mi][ni][3] + tk[ni * 2 + 1]) * vv[ni * 2 + 1];
        }
#pragma unroll
    for (int r = 0; r < 8; r++) {
        rs[r] += __shfl_xor_sync(0xffffffffu, rs[r], 1);
        rs[r] += __shfl_xor_sync(0xffffffffu, rs[r], 2);
    }
    if (tid4 == 0) {
#pragma unroll
        for (int mi = 0; mi < 4; mi++) {
            int row0 = wm * 64 + mi * 16 + grp;
            atomicAdd(&part[row0],     rs[mi * 2]);
            atomicAdd(&part[row0 + 8], rs[mi * 2 + 1]);
        }
    }
    __syncthreads();
    if (tid < 128) atomicAdd(&g_scores[b * SS + s0 + tid], part[tid]);
}

// ---------------------------------------------------------------------------
// Kernel 3: softmax over S per batch; writes weights to d_out
// ---------------------------------------------------------------------------
__global__ void __launch_bounds__(256) k_softmax(float* __restrict__ wout) {
    const int b = blockIdx.x, tid = threadIdx.x;
    __shared__ float red[256];
    float v[8];
    float mx = -1e30f;
#pragma unroll
    for (int i = 0; i < 8; i++) {
        v[i] = g_scores[b * SS + tid + i * 256];
        mx = fmaxf(mx, v[i]);
    }
    red[tid] = mx; __syncthreads();
    for (int o = 128; o; o >>= 1) {
        if (tid < o) red[tid] = fmaxf(red[tid], red[tid + o]);
        __syncthreads();
    }
    mx = red[0]; __syncthreads();

    float sum = 0.0f;
#pragma unroll
    for (int i = 0; i < 8; i++) { v[i] = expf(v[i] - mx); sum += v[i]; }
    red[tid] = sum; __syncthreads();
    for (int o = 128; o; o >>= 1) {
        if (tid < o) red[tid] += red[tid + o];
        __syncthreads();
    }
    float inv = 1.0f / red[0];
#pragma unroll
    for (int i = 0; i < 8; i++) wout[b * SS + tid + i * 256] = v[i] * inv;
}

// ---------------------------------------------------------------------------
// Kernel 4: context[b,h] = sum_s w[b,s] * keys[b,s,h]   (split over S, atomics)
// grid (H/128=8, B=32, 4 s-chunks), 128 threads
// ---------------------------------------------------------------------------
__global__ void __launch_bounds__(128) k_context(const float* __restrict__ keys,
                                                 const float* __restrict__ w,
                                                 float* __restrict__ ctx) {
    const int b = blockIdx.y;
    const int h = blockIdx.x * 128 + threadIdx.x;
    const int s0 = blockIdx.z * (SS / 4);
    const float* kb = keys + (size_t)b * SS * HH + (size_t)s0 * HH + h;
    const float* wb = w + b * SS + s0;
    float acc = 0.0f;
#pragma unroll 8
    for (int s = 0; s < SS / 4; s++) acc += wb[s] * kb[(size_t)s * HH];
    atomicAdd(&ctx[b * HH + h], acc);
}

// ---------------------------------------------------------------------------
// launch
// ---------------------------------------------------------------------------
extern "C" void kernel_launch(void* const* d_in, const int* in_sizes, int n_in,
                              void* d_out, int out_size) {
    const float* query = (const float*)d_in[0];
    const float* keys  = (const float*)d_in[1];
    const float* Wa_w  = (const float*)d_in[2];
    const float* Wa_b  = (const float*)d_in[3];
    const float* Ua_w  = (const float*)d_in[4];
    const float* Ua_b  = (const float*)d_in[5];
    const float* Va_w  = (const float*)d_in[6];
    const float* Va_b  = (const float*)d_in[7];

    float* out = (float*)d_out;
    float* ctx = out;                 // [B,1,H] = 32768 floats
    float* wts = out + BB * HH;       // [B,1,S] = 65536 floats

    const int smem_bytes = 4 * TILEF * (int)sizeof(float);   // 73728
    cudaFuncSetAttribute(k_main, cudaFuncAttributeMaxDynamicSharedMemorySize,
                         smem_bytes);

    k_init<<<(BB * SS + 255) / 256, 256>>>(Va_b, ctx);
    k_qproj<<<(BB * HH) / 8, 256>>>(query, Wa_w, Wa_b, Ua_b);
    k_main<<<dim3(SS / 128, HH / 128, BB), 256, smem_bytes>>>(keys, Ua_w, Va_w);
    k_softmax<<<BB, 256>>>(wts);
    k_context<<<dim3(HH / 128, BB, 4), 128>>>(keys, wts, ctx);
}

// round 9
// speedup vs baseline: 1.4341x; 1.4341x over previous
#include <cuda_runtime.h>
#include <cstdint>

// Problem constants
#define BB 32
#define SS 2048
#define HH 1024

// Scratch (no allocations allowed)
__device__ float g_t[BB * HH];       // q_proj + Wa_b + Ua_b, per (b,k)
__device__ float g_scores[BB * SS];  // attention scores

// ---------------------------------------------------------------------------
// helpers
// ---------------------------------------------------------------------------
__device__ __forceinline__ void cp16(float* dst, const float* src) {
    unsigned d = (unsigned)__cvta_generic_to_shared(dst);
    asm volatile("cp.async.cg.shared.global [%0], [%1], 16;" :: "r"(d), "l"(src));
}

__device__ __forceinline__ void mma_tf32(float c[4], const unsigned a[4],
                                         unsigned b0, unsigned b1) {
    asm volatile(
        "mma.sync.aligned.m16n8k8.row.col.f32.tf32.tf32.f32 "
        "{%0,%1,%2,%3},{%4,%5,%6,%7},{%8,%9},{%0,%1,%2,%3};"
        : "+f"(c[0]), "+f"(c[1]), "+f"(c[2]), "+f"(c[3])
        : "r"(a[0]), "r"(a[1]), "r"(a[2]), "r"(a[3]), "r"(b0), "r"(b1));
}

// fast tanh: 1 - 2/(e^{2x}+1). Saturates correctly at +/-inf. ~6 instrs.
__device__ __forceinline__ float tanh_e(float x) {
    float ex = __expf(2.0f * x);
    return 1.0f - __fdividef(2.0f, ex + 1.0f);
}

// ---------------------------------------------------------------------------
// Kernel 0: init scores = Va_b, context region of d_out = 0
// ---------------------------------------------------------------------------
__global__ void k_init(const float* __restrict__ Va_b, float* __restrict__ ctx) {
    int i = blockIdx.x * blockDim.x + threadIdx.x;
    if (i < BB * SS) g_scores[i] = Va_b[0];
    if (i < BB * HH) ctx[i] = 0.0f;
}

// ---------------------------------------------------------------------------
// Kernel 1: g_t[b,k] = sum_h query[b,h] * Wa_w[k,h] + Wa_b[k] + Ua_b[k]
// one warp per (b,k)
// ---------------------------------------------------------------------------
__global__ void __launch_bounds__(256) k_qproj(const float* __restrict__ q,
                                               const float* __restrict__ W,
                                               const float* __restrict__ Wb,
                                               const float* __restrict__ Ub) {
    int w = (blockIdx.x * blockDim.x + threadIdx.x) >> 5;
    int lane = threadIdx.x & 31;
    int b = w >> 10;          // / HH (1024)
    int k = w & 1023;
    const float* qr = q + (size_t)b * HH;
    const float* wr = W + (size_t)k * HH;
    float acc = 0.0f;
#pragma unroll 8
    for (int h = lane; h < HH; h += 32) acc += qr[h] * wr[h];
#pragma unroll
    for (int o = 16; o; o >>= 1) acc += __shfl_xor_sync(0xffffffffu, acc, o);
    if (lane == 0) g_t[b * HH + k] = acc + Wb[k] + Ub[k];
}

// ---------------------------------------------------------------------------
// Kernel 2 (main): fused  tanh(keys@Ua^T + t) . Va  ->  atomic scores
// CTA tile: 128 (s) x 128 (k_out), K-chunk 32, tf32 mma.sync (operands passed
// as raw fp32 bits -> tf32 truncation, no cvt), cp.async double buffer.
// grid: (S/128=16, H/128=8, B=32), 256 threads (8 warps, 2x4 warp grid)
// ---------------------------------------------------------------------------
#define SROW 36                 // padded smem row stride (floats) -> conflict free
#define TILEF (128 * SROW)      // floats per tile buffer

__global__ void __launch_bounds__(256, 2) k_main(const float* __restrict__ keys,
                                                 const float* __restrict__ Ua,
                                                 const float* __restrict__ Va) {
    extern __shared__ float sm[];
    float* Abuf[2] = { sm,           sm + 2 * TILEF };
    float* Bbuf[2] = { sm + TILEF,   sm + 3 * TILEF };

    const int b  = blockIdx.z;
    const int s0 = blockIdx.x * 128;
    const int k0 = blockIdx.y * 128;
    const int tid = threadIdx.x;

    const float* Ag = keys + ((size_t)b * SS + s0) * HH;   // + row*HH + h
    const float* Bg = Ua + (size_t)k0 * HH;                // + row*HH + h

    const int lane = tid & 31, warp = tid >> 5;
    const int wm = warp >> 2, wn = warp & 3;               // 2 x 4 warp grid
    const int grp = lane >> 2, tid4 = lane & 3;

    float c[4][4][4];
#pragma unroll
    for (int mi = 0; mi < 4; mi++)
#pragma unroll
        for (int ni = 0; ni < 4; ni++)
#pragma unroll
            for (int r = 0; r < 4; r++) c[mi][ni][r] = 0.0f;

    // loader: 128 rows x 32 floats per tile; 256 threads x 4 float4 each (A and B)
    auto load_stage = [&](int st, int h0) {
#pragma unroll
        for (int p = 0; p < 4; p++) {
            int id  = tid + p * 256;
            int row = id >> 3;
            int c4  = (id & 7) * 4;
            cp16(Abuf[st] + row * SROW + c4, Ag + (size_t)row * HH + h0 + c4);
            cp16(Bbuf[st] + row * SROW + c4, Bg + (size_t)row * HH + h0 + c4);
        }
    };

    int cur = 0;
    load_stage(0, 0);
    asm volatile("cp.async.commit_group;");

#pragma unroll 1
    for (int it = 0; it < HH / 32; ++it) {
        if (it < HH / 32 - 1) {
            load_stage(cur ^ 1, (it + 1) * 32);
            asm volatile("cp.async.commit_group;");
            asm volatile("cp.async.wait_group 1;");
        } else {
            asm volatile("cp.async.wait_group 0;");
        }
        __syncthreads();

        // raw fp32 bits fed to tf32 MMA (HW truncates low mantissa bits)
        const unsigned* A_ = reinterpret_cast<const unsigned*>(Abuf[cur]);
        const unsigned* B_ = reinterpret_cast<const unsigned*>(Bbuf[cur]);
#pragma unroll
        for (int ks = 0; ks < 4; ++ks) {
            unsigned af[4][4];
#pragma unroll
            for (int mi = 0; mi < 4; mi++) {
                const unsigned* ap = A_ + (wm * 64 + mi * 16 + grp) * SROW + ks * 8 + tid4;
                af[mi][0] = ap[0];
                af[mi][1] = ap[8 * SROW];
                af[mi][2] = ap[4];
                af[mi][3] = ap[8 * SROW + 4];
            }
#pragma unroll
            for (int ni = 0; ni < 4; ni++) {
                const unsigned* bp = B_ + (wn * 32 + ni * 8 + grp) * SROW + ks * 8 + tid4;
                unsigned b0 = bp[0];
                unsigned b1 = bp[4];
#pragma unroll
                for (int mi = 0; mi < 4; mi++) mma_tf32(c[mi][ni], af[mi], b0, b1);
            }
        }
        __syncthreads();
        cur ^= 1;
    }

    // ---- epilogue: tanh(C + t) * Va, reduce over k within tile ----
    float* part = sm;                 // reuse tile smem (safe after trailing sync)
    if (tid < 128) part[tid] = 0.0f;
    __syncthreads();

    float tk[8], vv[8];
#pragma unroll
    for (int ni = 0; ni < 4; ni++) {
        int kc = k0 + wn * 32 + ni * 8 + 2 * tid4;
        tk[ni * 2]     = g_t[b * HH + kc];
        tk[ni * 2 + 1] = g_t[b * HH + kc + 1];
        vv[ni * 2]     = Va[kc];
        vv[ni * 2 + 1] = Va[kc + 1];
    }

    float rs[8];
#pragma unroll
    for (int r = 0; r < 8; r++) rs[r] = 0.0f;
#pragma unroll
    for (int mi = 0; mi < 4; mi++)
#pragma unroll
        for (int ni = 0; ni < 4; ni++) {
            rs[mi * 2]     += tanh_e(c[mi][ni][0] + tk[ni * 2])     * vv[ni * 2]
                            + tanh_e(c[mi][ni][1] + tk[ni * 2 + 1]) * vv[ni * 2 + 1];
            rs[mi * 2 + 1] += tanh_e(c[mi][ni][2] + tk[ni * 2])     * vv[ni * 2]
                            + tanh_e(c[mi][ni][3] + tk[ni * 2 + 1]) * vv[ni * 2 + 1];
        }
#pragma unroll
    for (int r = 0; r < 8; r++) {
        rs[r] += __shfl_xor_sync(0xffffffffu, rs[r], 1);
        rs[r] += __shfl_xor_sync(0xffffffffu, rs[r], 2);
    }
    if (tid4 == 0) {
#pragma unroll
        for (int mi = 0; mi < 4; mi++) {
            int row0 = wm * 64 + mi * 16 + grp;
            atomicAdd(&part[row0],     rs[mi * 2]);
            atomicAdd(&part[row0 + 8], rs[mi * 2 + 1]);
        }
    }
    __syncthreads();
    if (tid < 128) atomicAdd(&g_scores[b * SS + s0 + tid], part[tid]);
}

// ---------------------------------------------------------------------------
// Kernel 3: softmax over S per batch; writes weights to d_out
// ---------------------------------------------------------------------------
__global__ void __launch_bounds__(256) k_softmax(float* __restrict__ wout) {
    const int b = blockIdx.x, tid = threadIdx.x;
    __shared__ float red[256];
    float v[8];
    float mx = -1e30f;
#pragma unroll
    for (int i = 0; i < 8; i++) {
        v[i] = g_scores[b * SS + tid + i * 256];
        mx = fmaxf(mx, v[i]);
    }
    red[tid] = mx; __syncthreads();
    for (int o = 128; o; o >>= 1) {
        if (tid < o) red[tid] = fmaxf(red[tid], red[tid + o]);
        __syncthreads();
    }
    mx = red[0]; __syncthreads();

    float sum = 0.0f;
#pragma unroll
    for (int i = 0; i < 8; i++) { v[i] = expf(v[i] - mx); sum += v[i]; }
    red[tid] = sum; __syncthreads();
    for (int o = 128; o; o >>= 1) {
        if (tid < o) red[tid] += red[tid + o];
        __syncthreads();
    }
    float inv = 1.0f / red[0];
#pragma unroll
    for (int i = 0; i < 8; i++) wout[b * SS + tid + i * 256] = v[i] * inv;
}

// ---------------------------------------------------------------------------
// Kernel 4: context[b,h] = sum_s w[b,s] * keys[b,s,h]   (split over S, atomics)
// grid (H/128=8, B=32, 4 s-chunks), 128 threads
// ---------------------------------------------------------------------------
__global__ void __launch_bounds__(128) k_context(const float* __restrict__ keys,
                                                 const float* __restrict__ w,
                                                 float* __restrict__ ctx) {
    const int b = blockIdx.y;
    const int h = blockIdx.x * 128 + threadIdx.x;
    const int s0 = blockIdx.z * (SS / 4);
    const float* kb = keys + (size_t)b * SS * HH + (size_t)s0 * HH + h;
    const float* wb = w + b * SS + s0;
    float acc = 0.0f;
#pragma unroll 8
    for (int s = 0; s < SS / 4; s++) acc += wb[s] * kb[(size_t)s * HH];
    atomicAdd(&ctx[b * HH + h], acc);
}

// ---------------------------------------------------------------------------
// launch
// ---------------------------------------------------------------------------
extern "C" void kernel_launch(void* const* d_in, const int* in_sizes, int n_in,
                              void* d_out, int out_size) {
    const float* query = (const float*)d_in[0];
    const float* keys  = (const float*)d_in[1];
    const float* Wa_w  = (const float*)d_in[2];
    const float* Wa_b  = (const float*)d_in[3];
    const float* Ua_w  = (const float*)d_in[4];
    const float* Ua_b  = (const float*)d_in[5];
    const float* Va_w  = (const float*)d_in[6];
    const float* Va_b  = (const float*)d_in[7];

    float* out = (float*)d_out;
    float* ctx = out;                 // [B,1,H] = 32768 floats
    float* wts = out + BB * HH;       // [B,1,S] = 65536 floats

    const int smem_bytes = 4 * TILEF * (int)sizeof(float);   // 73728
    cudaFuncSetAttribute(k_main, cudaFuncAttributeMaxDynamicSharedMemorySize,
                         smem_bytes);

    k_init<<<(BB * SS + 255) / 256, 256>>>(Va_b, ctx);
    k_qproj<<<(BB * HH) / 8, 256>>>(query, Wa_w, Wa_b, Ua_b);
    k_main<<<dim3(SS / 128, HH / 128, BB), 256, smem_bytes>>>(keys, Ua_w, Va_w);
    k_softmax<<<BB, 256>>>(wts);
    k_context<<<dim3(HH / 128, BB, 4), 128>>>(keys, wts, ctx);
}

// round 13
// speedup vs baseline: 1.5736x; 1.0972x over previous
#include <cuda_runtime.h>
#include <cstdint>

// Problem constants
#define BB 32
#define SS 2048
#define HH 1024

// Scratch (no allocations allowed)
__device__ float g_t[BB * HH];       // q_proj + Wa_b + Ua_b, per (b,k)
__device__ float g_scores[BB * SS];  // attention scores

// ---------------------------------------------------------------------------
// helpers
// ---------------------------------------------------------------------------
__device__ __forceinline__ void cp16(float* dst, const float* src) {
    unsigned d = (unsigned)__cvta_generic_to_shared(dst);
    asm volatile("cp.async.cg.shared.global [%0], [%1], 16;" :: "r"(d), "l"(src));
}

__device__ __forceinline__ void mma_tf32(float c[4], const unsigned a[4],
                                         unsigned b0, unsigned b1) {
    asm volatile(
        "mma.sync.aligned.m16n8k8.row.col.f32.tf32.tf32.f32 "
        "{%0,%1,%2,%3},{%4,%5,%6,%7},{%8,%9},{%0,%1,%2,%3};"
        : "+f"(c[0]), "+f"(c[1]), "+f"(c[2]), "+f"(c[3])
        : "r"(a[0]), "r"(a[1]), "r"(a[2]), "r"(a[3]), "r"(b0), "r"(b1));
}

// fast tanh: 1 - 2/(e^{2x}+1). Saturates correctly at +/-inf.
__device__ __forceinline__ float tanh_e(float x) {
    float ex = __expf(2.0f * x);
    return 1.0f - __fdividef(2.0f, ex + 1.0f);
}

// ---------------------------------------------------------------------------
// Kernel 0: init scores = Va_b, context region of d_out = 0
// ---------------------------------------------------------------------------
__global__ void k_init(const float* __restrict__ Va_b, float* __restrict__ ctx) {
    int i = blockIdx.x * blockDim.x + threadIdx.x;
    if (i < BB * SS) g_scores[i] = Va_b[0];
    if (i < BB * HH) ctx[i] = 0.0f;
}

// dummy no-op: shifts k_main into the ncu-captured launch slot
__global__ void k_dummy() {}

// ---------------------------------------------------------------------------
// Kernel 1: g_t[b,k] = sum_h query[b,h] * Wa_w[k,h] + Wa_b[k] + Ua_b[k]
// ---------------------------------------------------------------------------
__global__ void __launch_bounds__(256) k_qproj(const float* __restrict__ q,
                                               const float* __restrict__ W,
                                               const float* __restrict__ Wb,
                                               const float* __restrict__ Ub) {
    int w = (blockIdx.x * blockDim.x + threadIdx.x) >> 5;
    int lane = threadIdx.x & 31;
    int b = w >> 10;
    int k = w & 1023;
    const float* qr = q + (size_t)b * HH;
    const float* wr = W + (size_t)k * HH;
    float acc = 0.0f;
#pragma unroll 8
    for (int h = lane; h < HH; h += 32) acc += qr[h] * wr[h];
#pragma unroll
    for (int o = 16; o; o >>= 1) acc += __shfl_xor_sync(0xffffffffu, acc, o);
    if (lane == 0) g_t[b * HH + k] = acc + Wb[k] + Ub[k];
}

// ---------------------------------------------------------------------------
// Kernel 2 (main): fused  tanh(keys@Ua^T + t) . Va  ->  atomic scores
// CTA tile: 128 (s) x 256 (k_out), warp tile 64x64, K-chunk 32, tf32 mma.sync,
// 3-stage cp.async pipeline. grid (16, 4, 32), 256 threads, 1 CTA/SM.
// ---------------------------------------------------------------------------
#define SROW 36                   // padded smem row stride (floats)
#define A_TILE (128 * SROW)       // 4608 floats
#define B_TILE (256 * SROW)       // 9216 floats
#define STAGE_F (A_TILE + B_TILE) // 13824 floats = 55296 B
#define NSTG 3
#define SMEM_BYTES (NSTG * STAGE_F * 4)   // 165888

__global__ void __launch_bounds__(256, 1) k_main(const float* __restrict__ keys,
                                                 const float* __restrict__ Ua,
                                                 const float* __restrict__ Va) {
    extern __shared__ float sm[];
    __shared__ float s_tk[256], s_va[256];

    const int b  = blockIdx.z;
    const int s0 = blockIdx.x * 128;
    const int k0 = blockIdx.y * 256;
    const int tid = threadIdx.x;

    const float* Ag = keys + ((size_t)b * SS + s0) * HH;
    const float* Bg = Ua + (size_t)k0 * HH;

    const int lane = tid & 31, warp = tid >> 5;
    const int wm = warp >> 2, wn = warp & 3;          // 2 x 4 warp grid
    const int grp = lane >> 2, tid4 = lane & 3;

    float c[4][8][4];
#pragma unroll
    for (int mi = 0; mi < 4; mi++)
#pragma unroll
        for (int ni = 0; ni < 8; ni++)
#pragma unroll
            for (int r = 0; r < 4; r++) c[mi][ni][r] = 0.0f;

    // loader: A 128 rows x 32 floats, B 256 rows x 32 floats per stage
    auto load_stage = [&](int st, int h0) {
        float* Ab = sm + st * STAGE_F;
        float* Bb = Ab + A_TILE;
#pragma unroll
        for (int p = 0; p < 4; p++) {                 // A: 1024 float4
            int id  = tid + p * 256;
            int row = id >> 3;
            int c4  = (id & 7) * 4;
            cp16(Ab + row * SROW + c4, Ag + (size_t)row * HH + h0 + c4);
        }
#pragma unroll
        for (int p = 0; p < 8; p++) {                 // B: 2048 float4
            int id  = tid + p * 256;
            int row = id >> 3;
            int c4  = (id & 7) * 4;
            cp16(Bb + row * SROW + c4, Bg + (size_t)row * HH + h0 + c4);
        }
        asm volatile("cp.async.commit_group;");
    };

    load_stage(0, 0);
    load_stage(1, 32);
    load_stage(2, 64);

#pragma unroll 1
    for (int it = 0; it < HH / 32; ++it) {
        if (it < HH / 32 - 2)      asm volatile("cp.async.wait_group 2;");
        else if (it < HH / 32 - 1) asm volatile("cp.async.wait_group 1;");
        else                       asm volatile("cp.async.wait_group 0;");
        __syncthreads();

        const int st = it % NSTG;
        const unsigned* A_ = reinterpret_cast<const unsigned*>(sm + st * STAGE_F);
        const unsigned* B_ = A_ + A_TILE;
#pragma unroll
        for (int ks = 0; ks < 4; ++ks) {
            unsigned af[4][4];
#pragma unroll
            for (int mi = 0; mi < 4; mi++) {
                const unsigned* ap = A_ + (wm * 64 + mi * 16 + grp) * SROW + ks * 8 + tid4;
                af[mi][0] = ap[0];
                af[mi][1] = ap[8 * SROW];
                af[mi][2] = ap[4];
                af[mi][3] = ap[8 * SROW + 4];
            }
#pragma unroll
            for (int ni = 0; ni < 8; ni++) {
                const unsigned* bp = B_ + (wn * 64 + ni * 8 + grp) * SROW + ks * 8 + tid4;
                unsigned b0 = bp[0];
                unsigned b1 = bp[4];
#pragma unroll
                for (int mi = 0; mi < 4; mi++) mma_tf32(c[mi][ni], af[mi], b0, b1);
            }
        }
        __syncthreads();
        if (it + NSTG < HH / 32) load_stage(it % NSTG, (it + NSTG) * 32);
    }

    // ---- epilogue: tanh(C + t) * Va, reduce over k within tile ----
    s_tk[tid] = g_t[b * HH + k0 + tid];
    s_va[tid] = Va[k0 + tid];
    float* part = sm;                  // reuse dynamic smem
    if (tid < 128) part[tid] = 0.0f;
    __syncthreads();

    float rs[8];
#pragma unroll
    for (int r = 0; r < 8; r++) rs[r] = 0.0f;
#pragma unroll
    for (int ni = 0; ni < 8; ni++) {
        int kc = wn * 64 + ni * 8 + 2 * tid4;
        float t0 = s_tk[kc], t1 = s_tk[kc + 1];
        float v0 = s_va[kc], v1 = s_va[kc + 1];
#pragma unroll
        for (int mi = 0; mi < 4; mi++) {
            rs[mi * 2]     += tanh_e(c[mi][ni][0] + t0) * v0
                            + tanh_e(c[mi][ni][1] + t1) * v1;
            rs[mi * 2 + 1] += tanh_e(c[mi][ni][2] + t0) * v0
                            + tanh_e(c[mi][ni][3] + t1) * v1;
        }
    }
#pragma unroll
    for (int r = 0; r < 8; r++) {
        rs[r] += __shfl_xor_sync(0xffffffffu, rs[r], 1);
        rs[r] += __shfl_xor_sync(0xffffffffu, rs[r], 2);
    }
    if (tid4 == 0) {
#pragma unroll
        for (int mi = 0; mi < 4; mi++) {
            int row0 = wm * 64 + mi * 16 + grp;
            atomicAdd(&part[row0],     rs[mi * 2]);
            atomicAdd(&part[row0 + 8], rs[mi * 2 + 1]);
        }
    }
    __syncthreads();
    if (tid < 128) atomicAdd(&g_scores[b * SS + s0 + tid], part[tid]);
}

// ---------------------------------------------------------------------------
// Kernel 3: softmax over S per batch; writes weights to d_out
// ---------------------------------------------------------------------------
__global__ void __launch_bounds__(256) k_softmax(float* __restrict__ wout) {
    const int b = blockIdx.x, tid = threadIdx.x;
    __shared__ float red[256];
    float v[8];
    float mx = -1e30f;
#pragma unroll
    for (int i = 0; i < 8; i++) {
        v[i] = g_scores[b * SS + tid + i * 256];
        mx = fmaxf(mx, v[i]);
    }
    red[tid] = mx; __syncthreads();
    for (int o = 128; o; o >>= 1) {
        if (tid < o) red[tid] = fmaxf(red[tid], red[tid + o]);
        __syncthreads();
    }
    mx = red[0]; __syncthreads();

    float sum = 0.0f;
#pragma unroll
    for (int i = 0; i < 8; i++) { v[i] = expf(v[i] - mx); sum += v[i]; }
    red[tid] = sum; __syncthreads();
    for (int o = 128; o; o >>= 1) {
        if (tid < o) red[tid] += red[tid + o];
        __syncthreads();
    }
    float inv = 1.0f / red[0];
#pragma unroll
    for (int i = 0; i < 8; i++) wout[b * SS + tid + i * 256] = v[i] * inv;
}

// ---------------------------------------------------------------------------
// Kernel 4: context[b,h] = sum_s w[b,s] * keys[b,s,h]   (split over S, atomics)
// ---------------------------------------------------------------------------
__global__ void __launch_bounds__(128) k_context(const float* __restrict__ keys,
                                                 const float* __restrict__ w,
                                                 float* __restrict__ ctx) {
    const int b = blockIdx.y;
    const int h = blockIdx.x * 128 + threadIdx.x;
    const int s0 = blockIdx.z * (SS / 4);
    const float* kb = keys + (size_t)b * SS * HH + (size_t)s0 * HH + h;
    const float* wb = w + b * SS + s0;
    float acc = 0.0f;
#pragma unroll 8
    for (int s = 0; s < SS / 4; s++) acc += wb[s] * kb[(size_t)s * HH];
    atomicAdd(&ctx[b * HH + h], acc);
}

// ---------------------------------------------------------------------------
// launch
// ---------------------------------------------------------------------------
extern "C" void kernel_launch(void* const* d_in, const int* in_sizes, int n_in,
                              void* d_out, int out_size) {
    const float* query = (const float*)d_in[0];
    const float* keys  = (const float*)d_in[1];
    const float* Wa_w  = (const float*)d_in[2];
    const float* Wa_b  = (const float*)d_in[3];
    const float* Ua_w  = (const float*)d_in[4];
    const float* Ua_b  = (const float*)d_in[5];
    const float* Va_w  = (const float*)d_in[6];
    const float* Va_b  = (const float*)d_in[7];

    float* out = (float*)d_out;
    float* ctx = out;                 // [B,1,H] = 32768 floats
    float* wts = out + BB * HH;       // [B,1,S] = 65536 floats

    cudaFuncSetAttribute(k_main, cudaFuncAttributeMaxDynamicSharedMemorySize,
                         SMEM_BYTES);

    k_init<<<(BB * SS + 255) / 256, 256>>>(Va_b, ctx);
    k_qproj<<<(BB * HH) / 8, 256>>>(query, Wa_w, Wa_b, Ua_b);
    k_dummy<<<1, 1>>>();   // shifts k_main into the ncu captured launch slot
    k_main<<<dim3(SS / 128, HH / 256, BB), 256, SMEM_BYTES>>>(keys, Ua_w, Va_w);
    k_softmax<<<BB, 256>>>(wts);
    k_context<<<dim3(HH / 128, BB, 4), 128>>>(keys, wts, ctx);
}